// round 1
// baseline (speedup 1.0000x reference)
#include <cuda_runtime.h>
#include <math.h>

#define Bsz   8
#define Lsz   2048
#define Dsz   1024
#define BDsz  512
#define DINsz 1024
#define NSTsz 16
#define KCsz  4
#define DTRsz 32
#define Tsz   (Bsz*Lsz)   // 16384 tokens

// ---------------- scratch (device globals; no allocation allowed) -------------
__device__ __align__(256) float g_h   [Tsz*BDsz];        // 32 MB
__device__ __align__(256) float g_xz  [Tsz*2*DINsz];     // 128 MB
__device__ __align__(256) float g_xcs [Tsz*DINsz];       // 64 MB
__device__ __align__(256) float g_xdbl[Tsz*64];          // 4 MB
__device__ __align__(256) float g_dt  [Tsz*DINsz];       // 64 MB
__device__ __align__(256) float g_y   [Tsz*DINsz];       // 64 MB
__device__ __align__(256) float g_m   [Tsz*BDsz];        // 32 MB

// ---------------- generic fp32 SGEMM: C = A(MxK) * B(KxN) (+bias, +act) -------
// EPI: 0 = none, 1 = bias, 2 = bias + softplus
#define GBM 128
#define GBN 128
#define GBK 16

__device__ __forceinline__ float softplus_f(float v) {
    return v > 20.f ? v : log1pf(expf(v));
}

template<int EPI>
__global__ void sgemm_kernel(int M, int N, int K, int lda, int ldb, int ldc,
                             const float* __restrict__ A, const float* __restrict__ B,
                             const float* __restrict__ bias, float* __restrict__ C)
{
    __shared__ float As[GBK][GBM];
    __shared__ float Bs[GBK][GBN];

    const int tid = threadIdx.x;                 // 256 threads
    const int bm = blockIdx.y * GBM;
    const int bn = blockIdx.x * GBN;

    const int aRow = tid >> 2;                   // 0..63
    const int aCol = (tid & 3) << 2;             // 0,4,8,12
    const int bRow = tid >> 5;                   // 0..7
    const int bCol = (tid & 31) << 2;            // 0..124

    const int ty = tid >> 4;                     // 0..15
    const int tx = tid & 15;                     // 0..15

    float acc[8][8];
#pragma unroll
    for (int i = 0; i < 8; i++)
#pragma unroll
        for (int j = 0; j < 8; j++) acc[i][j] = 0.f;

    for (int k0 = 0; k0 < K; k0 += GBK) {
        // ---- load A tile (128 x 16), store transposed ----
#pragma unroll
        for (int i = 0; i < 2; i++) {
            int r = aRow + i * 64;
            float4 v = *(const float4*)&A[(size_t)(bm + r) * lda + (k0 + aCol)];
            As[aCol + 0][r] = v.x;
            As[aCol + 1][r] = v.y;
            As[aCol + 2][r] = v.z;
            As[aCol + 3][r] = v.w;
        }
        // ---- load B tile (16 x 128) ----
#pragma unroll
        for (int i = 0; i < 2; i++) {
            int r = bRow + i * 8;
            float4 v;
            if (bn + bCol < N)
                v = *(const float4*)&B[(size_t)(k0 + r) * ldb + (bn + bCol)];
            else
                v = make_float4(0.f, 0.f, 0.f, 0.f);
            *(float4*)&Bs[r][bCol] = v;
        }
        __syncthreads();

#pragma unroll
        for (int kk = 0; kk < GBK; kk++) {
            float ar[8], br[8];
#pragma unroll
            for (int i = 0; i < 8; i++) ar[i] = As[kk][ty * 8 + i];
#pragma unroll
            for (int j = 0; j < 8; j++) br[j] = Bs[kk][tx * 8 + j];
#pragma unroll
            for (int i = 0; i < 8; i++)
#pragma unroll
                for (int j = 0; j < 8; j++)
                    acc[i][j] = fmaf(ar[i], br[j], acc[i][j]);
        }
        __syncthreads();
    }

    // ---- epilogue ----
#pragma unroll
    for (int i = 0; i < 8; i++) {
        int row = bm + ty * 8 + i;
#pragma unroll
        for (int jj = 0; jj < 8; jj += 4) {
            int col = bn + tx * 8 + jj;
            if (col < N) {
                float4 v;
                float o0 = acc[i][jj + 0], o1 = acc[i][jj + 1];
                float o2 = acc[i][jj + 2], o3 = acc[i][jj + 3];
                if (EPI >= 1) {
                    o0 += __ldg(&bias[col + 0]);
                    o1 += __ldg(&bias[col + 1]);
                    o2 += __ldg(&bias[col + 2]);
                    o3 += __ldg(&bias[col + 3]);
                }
                if (EPI == 2) {
                    o0 = softplus_f(o0); o1 = softplus_f(o1);
                    o2 = softplus_f(o2); o3 = softplus_f(o3);
                }
                v.x = o0; v.y = o1; v.z = o2; v.w = o3;
                *(float4*)&C[(size_t)row * ldc + col] = v;
            }
        }
    }
}

// ---------------- causal depthwise conv (K=4) + SiLU --------------------------
__global__ void conv_silu_kernel(const float* __restrict__ xz,
                                 const float* __restrict__ conv_w,
                                 const float* __restrict__ conv_b,
                                 float* __restrict__ out)
{
    int idx = blockIdx.x * blockDim.x + threadIdx.x;   // Tsz*DINsz total
    int d = idx & (DINsz - 1);
    int t = idx >> 10;                                  // token index (b*L + l)
    int l = t & (Lsz - 1);

    float acc = __ldg(&conv_b[d]);
#pragma unroll
    for (int k = 0; k < KCsz; k++) {
        int ls = l + k - (KCsz - 1);
        if (ls >= 0)
            acc = fmaf(xz[(size_t)(t + k - (KCsz - 1)) * (2 * DINsz) + d],
                       __ldg(&conv_w[d * KCsz + k]), acc);
    }
    float s = 1.f / (1.f + expf(-acc));
    out[idx] = acc * s;
}

// ---------------- selective scan (fused skip + gate) ---------------------------
// one thread per (b, d) channel, 16 states in registers; one warp per block so
// B_t/C_t (32 floats) load as a single coalesced 128B transaction into shared.
__global__ void scan_kernel(const float* __restrict__ dt,
                            const float* __restrict__ xdbl,
                            const float* __restrict__ xcs,
                            const float* __restrict__ xz,
                            const float* __restrict__ A_log,
                            const float* __restrict__ D_skip,
                            float* __restrict__ y)
{
    const int b = blockIdx.y;
    const int d = blockIdx.x * 32 + threadIdx.x;
    const int lane = threadIdx.x;

    float An[NSTsz];
#pragma unroll
    for (int n = 0; n < NSTsz; n++) An[n] = -expf(A_log[d * NSTsz + n]);

    float h[NSTsz];
#pragma unroll
    for (int n = 0; n < NSTsz; n++) h[n] = 0.f;

    const float Dv = D_skip[d];

    __shared__ float sBC[32];

    for (int l = 0; l < Lsz; l++) {
        const int t = b * Lsz + l;
        const float dtv = dt[(size_t)t * DINsz + d];
        const float xv  = xcs[(size_t)t * DINsz + d];
        sBC[lane] = xdbl[(size_t)t * 64 + DTRsz + lane];  // B[0..15], C[0..15]
        __syncwarp();

        const float dtx = dtv * xv;
        float yv = 0.f;
#pragma unroll
        for (int n = 0; n < NSTsz; n++) {
            float dA = __expf(dtv * An[n]);
            h[n] = fmaf(h[n], dA, dtx * sBC[n]);
            yv = fmaf(h[n], sBC[NSTsz + n], yv);
        }
        const float zv = xz[(size_t)t * (2 * DINsz) + DINsz + d];
        const float sz = zv / (1.f + __expf(-zv));
        y[(size_t)t * DINsz + d] = (yv + Dv * xv) * sz;
        __syncwarp();
    }
}

// ---------------- LayerNorm over 512 (one warp per row, in place) --------------
__global__ void ln_kernel(float* __restrict__ m,
                          const float* __restrict__ g,
                          const float* __restrict__ b)
{
    const int warp = threadIdx.x >> 5;
    const int lane = threadIdx.x & 31;
    const int row = blockIdx.x * 8 + warp;

    float4* p = (float4*)(m + (size_t)row * BDsz);
    float4 v[4];
    float s = 0.f, ss = 0.f;
#pragma unroll
    for (int i = 0; i < 4; i++) {
        v[i] = p[lane + i * 32];
        s  += v[i].x + v[i].y + v[i].z + v[i].w;
        ss += v[i].x * v[i].x + v[i].y * v[i].y + v[i].z * v[i].z + v[i].w * v[i].w;
    }
#pragma unroll
    for (int o = 16; o > 0; o >>= 1) {
        s  += __shfl_xor_sync(0xFFFFFFFF, s, o);
        ss += __shfl_xor_sync(0xFFFFFFFF, ss, o);
    }
    const float mu = s * (1.f / BDsz);
    const float var = ss * (1.f / BDsz) - mu * mu;
    const float r = rsqrtf(var + 1e-5f);
#pragma unroll
    for (int i = 0; i < 4; i++) {
        int col = (lane + i * 32) * 4;
        float4 o;
        o.x = (v[i].x - mu) * r * __ldg(&g[col + 0]) + __ldg(&b[col + 0]);
        o.y = (v[i].y - mu) * r * __ldg(&g[col + 1]) + __ldg(&b[col + 1]);
        o.z = (v[i].z - mu) * r * __ldg(&g[col + 2]) + __ldg(&b[col + 2]);
        o.w = (v[i].w - mu) * r * __ldg(&g[col + 3]) + __ldg(&b[col + 3]);
        p[lane + i * 32] = o;
    }
}

// ------------------------------- launch ---------------------------------------
extern "C" void kernel_launch(void* const* d_in, const int* in_sizes, int n_in,
                              void* d_out, int out_size)
{
    const float* x      = (const float*)d_in[0];
    const float* W_down = (const float*)d_in[1];
    const float* b_down = (const float*)d_in[2];
    const float* W_in   = (const float*)d_in[3];
    const float* conv_w = (const float*)d_in[4];
    const float* conv_b = (const float*)d_in[5];
    const float* W_x    = (const float*)d_in[6];
    const float* W_dt   = (const float*)d_in[7];
    const float* b_dt   = (const float*)d_in[8];
    const float* A_log  = (const float*)d_in[9];
    const float* D_skip = (const float*)d_in[10];
    const float* W_out  = (const float*)d_in[11];
    const float* ln_g   = (const float*)d_in[12];
    const float* ln_b   = (const float*)d_in[13];
    const float* W_up   = (const float*)d_in[14];
    const float* b_up   = (const float*)d_in[15];
    float* out = (float*)d_out;

    float *ph, *pxz, *pxcs, *pxdbl, *pdt, *py, *pm;
    cudaGetSymbolAddress((void**)&ph,    g_h);
    cudaGetSymbolAddress((void**)&pxz,   g_xz);
    cudaGetSymbolAddress((void**)&pxcs,  g_xcs);
    cudaGetSymbolAddress((void**)&pxdbl, g_xdbl);
    cudaGetSymbolAddress((void**)&pdt,   g_dt);
    cudaGetSymbolAddress((void**)&py,    g_y);
    cudaGetSymbolAddress((void**)&pm,    g_m);

    const int M = Tsz;
    dim3 blk(256);

    // 1) h = x @ W_down + b_down      [16384,1024]x[1024,512]
    {
        dim3 grid((BDsz + GBN - 1) / GBN, M / GBM);
        sgemm_kernel<1><<<grid, blk>>>(M, BDsz, Dsz, Dsz, BDsz, BDsz, x, W_down, b_down, ph);
    }
    // 2) xz = h @ W_in                [16384,512]x[512,2048]
    {
        dim3 grid((2 * DINsz + GBN - 1) / GBN, M / GBM);
        sgemm_kernel<0><<<grid, blk>>>(M, 2 * DINsz, BDsz, BDsz, 2 * DINsz, 2 * DINsz, ph, W_in, nullptr, pxz);
    }
    // 3) conv(K=4, causal) + silu -> xcs
    {
        int total = Tsz * DINsz;
        conv_silu_kernel<<<total / 256, 256>>>(pxz, conv_w, conv_b, pxcs);
    }
    // 4) x_dbl = xcs @ W_x            [16384,1024]x[1024,64]
    {
        dim3 grid((64 + GBN - 1) / GBN, M / GBM);
        sgemm_kernel<0><<<grid, blk>>>(M, 64, DINsz, DINsz, 64, 64, pxcs, W_x, nullptr, pxdbl);
    }
    // 5) dt = softplus(x_dbl[:, :32] @ W_dt + b_dt)   [16384,32]x[32,1024]
    {
        dim3 grid((DINsz + GBN - 1) / GBN, M / GBM);
        sgemm_kernel<2><<<grid, blk>>>(M, DINsz, DTRsz, 64, DINsz, DINsz, pxdbl, W_dt, b_dt, pdt);
    }
    // 6) selective scan + skip + gate -> y
    {
        dim3 grid(DINsz / 32, Bsz);
        scan_kernel<<<grid, 32>>>(pdt, pxdbl, pxcs, pxz, A_log, D_skip, py);
    }
    // 7) m = y @ W_out                [16384,1024]x[1024,512]
    {
        dim3 grid((BDsz + GBN - 1) / GBN, M / GBM);
        sgemm_kernel<0><<<grid, blk>>>(M, BDsz, DINsz, DINsz, BDsz, BDsz, py, W_out, nullptr, pm);
    }
    // 8) LayerNorm(512) in place
    {
        ln_kernel<<<M / 8, 256>>>(pm, ln_g, ln_b);
    }
    // 9) out = m @ W_up + b_up        [16384,512]x[512,1024]
    {
        dim3 grid((Dsz + GBN - 1) / GBN, M / GBM);
        sgemm_kernel<1><<<grid, blk>>>(M, Dsz, BDsz, BDsz, Dsz, Dsz, pm, W_up, b_up, out);
    }
}

// round 2
// speedup vs baseline: 1.1634x; 1.1634x over previous
#include <cuda_runtime.h>
#include <math.h>
#include <stdint.h>

#define Bsz   8
#define Lsz   2048
#define Dsz   1024
#define BDsz  512
#define DINsz 1024
#define NSTsz 16
#define KCsz  4
#define DTRsz 32
#define Tsz   (Bsz*Lsz)   // 16384 tokens

// ---------------- scratch (device globals; no allocation allowed) -------------
__device__ __align__(256) float g_h   [Tsz*BDsz];
__device__ __align__(256) float g_xz  [Tsz*2*DINsz];
__device__ __align__(256) float g_xcs [Tsz*DINsz];
__device__ __align__(256) float g_xdbl[Tsz*64];
__device__ __align__(256) float g_dt  [Tsz*DINsz];
__device__ __align__(256) float g_y   [Tsz*DINsz];
__device__ __align__(256) float g_m   [Tsz*BDsz];

// ---------------- helpers ------------------------------------------------------
__device__ __forceinline__ float softplus_f(float v) {
    return v > 20.f ? v : log1pf(expf(v));
}

__device__ __forceinline__ void tf32split(float x, uint32_t& hi, uint32_t& lo) {
    uint32_t h; asm("cvt.rna.tf32.f32 %0, %1;" : "=r"(h) : "f"(x));
    float l = x - __uint_as_float(h);
    uint32_t lw; asm("cvt.rna.tf32.f32 %0, %1;" : "=r"(lw) : "f"(l));
    hi = h; lo = lw;
}

__device__ __forceinline__ void mma_tf32(float* c, const uint32_t* a, const uint32_t* b) {
    asm volatile("mma.sync.aligned.m16n8k8.row.col.f32.tf32.tf32.f32 "
                 "{%0,%1,%2,%3}, {%4,%5,%6,%7}, {%8,%9}, {%0,%1,%2,%3};"
                 : "+f"(c[0]), "+f"(c[1]), "+f"(c[2]), "+f"(c[3])
                 : "r"(a[0]), "r"(a[1]), "r"(a[2]), "r"(a[3]), "r"(b[0]), "r"(b[1]));
}

__device__ __forceinline__ void cp_async16(void* smem_dst, const void* gmem_src) {
    uint32_t daddr = (uint32_t)__cvta_generic_to_shared(smem_dst);
    asm volatile("cp.async.ca.shared.global [%0], [%1], 16;\n" :: "r"(daddr), "l"(gmem_src));
}

// ---------------- TF32x3 tensor-core GEMM: C = A(MxK) * B(KxN) ------------------
// BM=128, BK=16 fixed. BN/WM template so N=64 case has no waste.
// EPI: 0 none, 1 bias, 2 bias + softplus
template<int BN, int WM, int EPI>
__global__ void __launch_bounds__(256, 1) mma_gemm(
    int M, int N, int K, int lda, int ldb, int ldc,
    const float* __restrict__ A, const float* __restrict__ B,
    const float* __restrict__ bias, float* __restrict__ C)
{
    constexpr int BM = 128, BK = 16;
    constexpr int WARPS_M = BM / WM;       // 2 (WM=64) or 4 (WM=32)
    constexpr int WARPS_N = 8 / WARPS_M;   // 4 or 2
    constexpr int WN = BN / WARPS_N;       // 32
    constexpr int MT = WM / 16;            // 4 or 2
    constexpr int NT = WN / 8;             // 4
    constexpr int ASTR = BK + 4;           // 20 floats: 20 ≡ 4 mod 32 -> conflict free frags
    constexpr int BSTR = BN + 4;           // 132 / 68: ≡ 4 mod 32

    __shared__ float As[2][BM * ASTR];
    __shared__ float Bs[2][BK * BSTR];

    const int tid = threadIdx.x;
    const int bm = blockIdx.y * BM;
    const int bn = blockIdx.x * BN;

    const int wid = tid >> 5, lane = tid & 31;
    const int wm = (wid % WARPS_M) * WM;
    const int wn = (wid / WARPS_M) * WN;
    const int lr = lane >> 2;   // 0..7
    const int lc = lane & 3;    // 0..3

    float acc[MT][NT][4];
#pragma unroll
    for (int i = 0; i < MT; i++)
#pragma unroll
        for (int j = 0; j < NT; j++)
#pragma unroll
            for (int r = 0; r < 4; r++) acc[i][j][r] = 0.f;

    const int ntiles = K / BK;

    // ---- async tile loader ----
    auto issue = [&](int buf, int k0) {
        // A tile: 128 x 16 floats = 512 float4, 2 per thread
#pragma unroll
        for (int i = 0; i < 2; i++) {
            int j = tid + i * 256;
            int r = j >> 2, c4 = (j & 3) << 2;
            cp_async16(&As[buf][r * ASTR + c4],
                       &A[(size_t)(bm + r) * lda + k0 + c4]);
        }
        // B tile: 16 x BN floats = BK*BN/4 float4
        constexpr int BF4 = BK * BN / 4;
#pragma unroll
        for (int i = 0; i < BF4 / 256 + (BF4 % 256 ? 1 : 0); i++) {
            int j = tid + i * 256;
            if (BF4 % 256 == 0 || j < BF4) {
                int k = j / (BN / 4), n4 = (j % (BN / 4)) << 2;
                cp_async16(&Bs[buf][k * BSTR + n4],
                           &B[(size_t)(k0 + k) * ldb + bn + n4]);
            }
        }
        asm volatile("cp.async.commit_group;\n");
    };

    issue(0, 0);

    for (int kt = 0; kt < ntiles; kt++) {
        if (kt + 1 < ntiles) {
            issue((kt + 1) & 1, (kt + 1) * BK);
            asm volatile("cp.async.wait_group 1;\n");
        } else {
            asm volatile("cp.async.wait_group 0;\n");
        }
        __syncthreads();

        const float* as = As[kt & 1];
        const float* bs = Bs[kt & 1];

#pragma unroll
        for (int ks = 0; ks < BK; ks += 8) {
            uint32_t ahi[MT][4], alo[MT][4];
#pragma unroll
            for (int mt = 0; mt < MT; mt++) {
                int m0 = wm + mt * 16 + lr;
                tf32split(as[m0 * ASTR + ks + lc],           ahi[mt][0], alo[mt][0]);
                tf32split(as[(m0 + 8) * ASTR + ks + lc],     ahi[mt][1], alo[mt][1]);
                tf32split(as[m0 * ASTR + ks + lc + 4],       ahi[mt][2], alo[mt][2]);
                tf32split(as[(m0 + 8) * ASTR + ks + lc + 4], ahi[mt][3], alo[mt][3]);
            }
            uint32_t bhi[NT][2], blo[NT][2];
#pragma unroll
            for (int nt = 0; nt < NT; nt++) {
                int n0 = wn + nt * 8 + lr;
                tf32split(bs[(ks + lc) * BSTR + n0],     bhi[nt][0], blo[nt][0]);
                tf32split(bs[(ks + lc + 4) * BSTR + n0], bhi[nt][1], blo[nt][1]);
            }
#pragma unroll
            for (int mt = 0; mt < MT; mt++)
#pragma unroll
                for (int nt = 0; nt < NT; nt++) {
                    mma_tf32(acc[mt][nt], ahi[mt], bhi[nt]);
                    mma_tf32(acc[mt][nt], ahi[mt], blo[nt]);
                    mma_tf32(acc[mt][nt], alo[mt], bhi[nt]);
                }
        }
        __syncthreads();
    }

    // ---- epilogue: float2 stores ----
#pragma unroll
    for (int mt = 0; mt < MT; mt++) {
        int row0 = bm + wm + mt * 16 + lr;
#pragma unroll
        for (int nt = 0; nt < NT; nt++) {
            int col = bn + wn + nt * 8 + lc * 2;
            float o0 = acc[mt][nt][0], o1 = acc[mt][nt][1];
            float o2 = acc[mt][nt][2], o3 = acc[mt][nt][3];
            if (EPI >= 1) {
                float bb0 = __ldg(&bias[col]), bb1 = __ldg(&bias[col + 1]);
                o0 += bb0; o1 += bb1; o2 += bb0; o3 += bb1;
            }
            if (EPI == 2) {
                o0 = softplus_f(o0); o1 = softplus_f(o1);
                o2 = softplus_f(o2); o3 = softplus_f(o3);
            }
            *(float2*)&C[(size_t)row0 * ldc + col]       = make_float2(o0, o1);
            *(float2*)&C[(size_t)(row0 + 8) * ldc + col] = make_float2(o2, o3);
        }
    }
}

// ---------------- causal depthwise conv (K=4) + SiLU --------------------------
__global__ void conv_silu_kernel(const float* __restrict__ xz,
                                 const float* __restrict__ conv_w,
                                 const float* __restrict__ conv_b,
                                 float* __restrict__ out)
{
    int idx = blockIdx.x * blockDim.x + threadIdx.x;
    int d = idx & (DINsz - 1);
    int t = idx >> 10;
    int l = t & (Lsz - 1);

    float acc = __ldg(&conv_b[d]);
#pragma unroll
    for (int k = 0; k < KCsz; k++) {
        int ls = l + k - (KCsz - 1);
        if (ls >= 0)
            acc = fmaf(xz[(size_t)(t + k - (KCsz - 1)) * (2 * DINsz) + d],
                       __ldg(&conv_w[d * KCsz + k]), acc);
    }
    float s = 1.f / (1.f + expf(-acc));
    out[idx] = acc * s;
}

// ---------------- selective scan (fused skip + gate) ---------------------------
__global__ void scan_kernel(const float* __restrict__ dt,
                            const float* __restrict__ xdbl,
                            const float* __restrict__ xcs,
                            const float* __restrict__ xz,
                            const float* __restrict__ A_log,
                            const float* __restrict__ D_skip,
                            float* __restrict__ y)
{
    const int b = blockIdx.y;
    const int d = blockIdx.x * 32 + threadIdx.x;
    const int lane = threadIdx.x;

    float An[NSTsz];
#pragma unroll
    for (int n = 0; n < NSTsz; n++) An[n] = -expf(A_log[d * NSTsz + n]);

    float h[NSTsz];
#pragma unroll
    for (int n = 0; n < NSTsz; n++) h[n] = 0.f;

    const float Dv = D_skip[d];
    __shared__ float sBC[32];

    for (int l = 0; l < Lsz; l++) {
        const int t = b * Lsz + l;
        const float dtv = dt[(size_t)t * DINsz + d];
        const float xv  = xcs[(size_t)t * DINsz + d];
        sBC[lane] = xdbl[(size_t)t * 64 + DTRsz + lane];
        __syncwarp();

        const float dtx = dtv * xv;
        float yv = 0.f;
#pragma unroll
        for (int n = 0; n < NSTsz; n++) {
            float dA = __expf(dtv * An[n]);
            h[n] = fmaf(h[n], dA, dtx * sBC[n]);
            yv = fmaf(h[n], sBC[NSTsz + n], yv);
        }
        const float zv = xz[(size_t)t * (2 * DINsz) + DINsz + d];
        const float sz = zv / (1.f + __expf(-zv));
        y[(size_t)t * DINsz + d] = (yv + Dv * xv) * sz;
        __syncwarp();
    }
}

// ---------------- LayerNorm over 512 (one warp per row, in place) --------------
__global__ void ln_kernel(float* __restrict__ m,
                          const float* __restrict__ g,
                          const float* __restrict__ b)
{
    const int warp = threadIdx.x >> 5;
    const int lane = threadIdx.x & 31;
    const int row = blockIdx.x * 8 + warp;

    float4* p = (float4*)(m + (size_t)row * BDsz);
    float4 v[4];
    float s = 0.f, ss = 0.f;
#pragma unroll
    for (int i = 0; i < 4; i++) {
        v[i] = p[lane + i * 32];
        s  += v[i].x + v[i].y + v[i].z + v[i].w;
        ss += v[i].x * v[i].x + v[i].y * v[i].y + v[i].z * v[i].z + v[i].w * v[i].w;
    }
#pragma unroll
    for (int o = 16; o > 0; o >>= 1) {
        s  += __shfl_xor_sync(0xFFFFFFFF, s, o);
        ss += __shfl_xor_sync(0xFFFFFFFF, ss, o);
    }
    const float mu = s * (1.f / BDsz);
    const float var = ss * (1.f / BDsz) - mu * mu;
    const float r = rsqrtf(var + 1e-5f);
#pragma unroll
    for (int i = 0; i < 4; i++) {
        int col = (lane + i * 32) * 4;
        float4 o;
        o.x = (v[i].x - mu) * r * __ldg(&g[col + 0]) + __ldg(&b[col + 0]);
        o.y = (v[i].y - mu) * r * __ldg(&g[col + 1]) + __ldg(&b[col + 1]);
        o.z = (v[i].z - mu) * r * __ldg(&g[col + 2]) + __ldg(&b[col + 2]);
        o.w = (v[i].w - mu) * r * __ldg(&g[col + 3]) + __ldg(&b[col + 3]);
        p[lane + i * 32] = o;
    }
}

// ------------------------------- launch ---------------------------------------
extern "C" void kernel_launch(void* const* d_in, const int* in_sizes, int n_in,
                              void* d_out, int out_size)
{
    const float* x      = (const float*)d_in[0];
    const float* W_down = (const float*)d_in[1];
    const float* b_down = (const float*)d_in[2];
    const float* W_in   = (const float*)d_in[3];
    const float* conv_w = (const float*)d_in[4];
    const float* conv_b = (const float*)d_in[5];
    const float* W_x    = (const float*)d_in[6];
    const float* W_dt   = (const float*)d_in[7];
    const float* b_dt   = (const float*)d_in[8];
    const float* A_log  = (const float*)d_in[9];
    const float* D_skip = (const float*)d_in[10];
    const float* W_out  = (const float*)d_in[11];
    const float* ln_g   = (const float*)d_in[12];
    const float* ln_b   = (const float*)d_in[13];
    const float* W_up   = (const float*)d_in[14];
    const float* b_up   = (const float*)d_in[15];
    float* out = (float*)d_out;

    float *ph, *pxz, *pxcs, *pxdbl, *pdt, *py, *pm;
    cudaGetSymbolAddress((void**)&ph,    g_h);
    cudaGetSymbolAddress((void**)&pxz,   g_xz);
    cudaGetSymbolAddress((void**)&pxcs,  g_xcs);
    cudaGetSymbolAddress((void**)&pxdbl, g_xdbl);
    cudaGetSymbolAddress((void**)&pdt,   g_dt);
    cudaGetSymbolAddress((void**)&py,    g_y);
    cudaGetSymbolAddress((void**)&pm,    g_m);

    const int M = Tsz;
    dim3 blk(256);

    // 1) h = x @ W_down + b_down      [16384,1024]x[1024,512]
    mma_gemm<128, 64, 1><<<dim3(BDsz / 128, M / 128), blk>>>(
        M, BDsz, Dsz, Dsz, BDsz, BDsz, x, W_down, b_down, ph);

    // 2) xz = h @ W_in                [16384,512]x[512,2048]
    mma_gemm<128, 64, 0><<<dim3(2 * DINsz / 128, M / 128), blk>>>(
        M, 2 * DINsz, BDsz, BDsz, 2 * DINsz, 2 * DINsz, ph, W_in, nullptr, pxz);

    // 3) conv(K=4, causal) + silu -> xcs
    conv_silu_kernel<<<(Tsz * DINsz) / 256, 256>>>(pxz, conv_w, conv_b, pxcs);

    // 4) x_dbl = xcs @ W_x            [16384,1024]x[1024,64]
    mma_gemm<64, 32, 0><<<dim3(1, M / 128), blk>>>(
        M, 64, DINsz, DINsz, 64, 64, pxcs, W_x, nullptr, pxdbl);

    // 5) dt = softplus(x_dbl[:, :32] @ W_dt + b_dt)   [16384,32]x[32,1024]
    mma_gemm<128, 64, 2><<<dim3(DINsz / 128, M / 128), blk>>>(
        M, DINsz, DTRsz, 64, DINsz, DINsz, pxdbl, W_dt, b_dt, pdt);

    // 6) selective scan + skip + gate -> y
    scan_kernel<<<dim3(DINsz / 32, Bsz), 32>>>(pdt, pxdbl, pxcs, pxz, A_log, D_skip, py);

    // 7) m = y @ W_out                [16384,1024]x[1024,512]
    mma_gemm<128, 64, 0><<<dim3(BDsz / 128, M / 128), blk>>>(
        M, BDsz, DINsz, DINsz, BDsz, BDsz, py, W_out, nullptr, pm);

    // 8) LayerNorm(512) in place
    ln_kernel<<<M / 8, 256>>>(pm, ln_g, ln_b);

    // 9) out = m @ W_up + b_up        [16384,512]x[512,1024]
    mma_gemm<128, 64, 1><<<dim3(Dsz / 128, M / 128), blk>>>(
        M, Dsz, BDsz, BDsz, Dsz, Dsz, pm, W_up, b_up, out);
}

// round 4
// speedup vs baseline: 1.4538x; 1.2496x over previous
#include <cuda_runtime.h>
#include <math.h>
#include <stdint.h>

#define Bsz   8
#define Lsz   2048
#define Dsz   1024
#define BDsz  512
#define DINsz 1024
#define NSTsz 16
#define KCsz  4
#define DTRsz 32
#define Tsz   (Bsz*Lsz)   // 16384 tokens

// ---------------- scratch (device globals; no allocation allowed) -------------
__device__ __align__(256) float g_h   [Tsz*BDsz];
__device__ __align__(256) float g_xz  [Tsz*2*DINsz];
__device__ __align__(256) float g_xcs [Tsz*DINsz];
__device__ __align__(256) float g_xdbl[Tsz*64];
__device__ __align__(256) float g_dt  [Tsz*DINsz];
__device__ __align__(256) float g_y   [Tsz*DINsz];
__device__ __align__(256) float g_m   [Tsz*BDsz];

// ---------------- helpers ------------------------------------------------------
__device__ __forceinline__ float softplus_f(float v) {
    return v > 20.f ? v : log1pf(expf(v));
}

// split a pair of fp32 into bf16x2 hi + bf16x2 lo (x1 goes to upper half)
__device__ __forceinline__ void bf16split2(float x0, float x1, uint32_t& hi, uint32_t& lo) {
    uint32_t h;
    asm("cvt.rn.bf16x2.f32 %0, %1, %2;" : "=r"(h) : "f"(x1), "f"(x0));
    float g0 = __uint_as_float(h << 16);
    float g1 = __uint_as_float(h & 0xffff0000u);
    float l0 = x0 - g0, l1 = x1 - g1;
    uint32_t lw;
    asm("cvt.rn.bf16x2.f32 %0, %1, %2;" : "=r"(lw) : "f"(l1), "f"(l0));
    hi = h; lo = lw;
}

__device__ __forceinline__ void mma_bf16(float* c, const uint32_t* a, const uint32_t* b) {
    asm volatile("mma.sync.aligned.m16n8k16.row.col.f32.bf16.bf16.f32 "
                 "{%0,%1,%2,%3}, {%4,%5,%6,%7}, {%8,%9}, {%0,%1,%2,%3};"
                 : "+f"(c[0]), "+f"(c[1]), "+f"(c[2]), "+f"(c[3])
                 : "r"(a[0]), "r"(a[1]), "r"(a[2]), "r"(a[3]), "r"(b[0]), "r"(b[1]));
}

__device__ __forceinline__ void cp_async16(void* smem_dst, const void* gmem_src) {
    uint32_t daddr = (uint32_t)__cvta_generic_to_shared(smem_dst);
    asm volatile("cp.async.ca.shared.global [%0], [%1], 16;\n" :: "r"(daddr), "l"(gmem_src));
}

// ---------------- bf16x3 tensor-core GEMM: C = A(MxK) * B(KxN) ------------------
// BM=128, BK=16 fixed. BN/WM template so N=64 case has no waste.
// EPI: 0 none, 1 bias, 2 bias + softplus
template<int BN, int WM, int EPI>
__global__ void __launch_bounds__(256, 2) mma_gemm(
    int M, int N, int K, int lda, int ldb, int ldc,
    const float* __restrict__ A, const float* __restrict__ B,
    const float* __restrict__ bias, float* __restrict__ C)
{
    constexpr int BM = 128, BK = 16;
    constexpr int WARPS_M = BM / WM;       // 2 (WM=64) or 4 (WM=32)
    constexpr int WARPS_N = 8 / WARPS_M;   // 4 or 2
    constexpr int WN = BN / WARPS_N;       // 32
    constexpr int MT = WM / 16;            // 4 or 2
    constexpr int NT = WN / 8;             // 4
    constexpr int ASTR = BK + 4;           // 20: rows 20 apart mod 32 -> conflict-free
    constexpr int BSTR = BN + 4;           // 132 / 68

    __shared__ float As[2][BM * ASTR];
    __shared__ float Bs[2][BK * BSTR];

    const int tid = threadIdx.x;
    const int bm = blockIdx.y * BM;
    const int bn = blockIdx.x * BN;

    const int wid = tid >> 5, lane = tid & 31;
    const int wm = (wid % WARPS_M) * WM;
    const int wn = (wid / WARPS_M) * WN;
    const int lr = lane >> 2;   // 0..7
    const int lc = lane & 3;    // 0..3

    float acc[MT][NT][4];
#pragma unroll
    for (int i = 0; i < MT; i++)
#pragma unroll
        for (int j = 0; j < NT; j++)
#pragma unroll
            for (int r = 0; r < 4; r++) acc[i][j][r] = 0.f;

    const int ntiles = K / BK;

    auto issue = [&](int buf, int k0) {
        // A tile: 128 x 16 floats = 512 float4, 2 per thread
#pragma unroll
        for (int i = 0; i < 2; i++) {
            int j = tid + i * 256;
            int r = j >> 2, c4 = (j & 3) << 2;
            cp_async16(&As[buf][r * ASTR + c4],
                       &A[(size_t)(bm + r) * lda + k0 + c4]);
        }
        // B tile: 16 x BN floats
        constexpr int BF4 = BK * BN / 4;
#pragma unroll
        for (int i = 0; i < BF4 / 256 + (BF4 % 256 ? 1 : 0); i++) {
            int j = tid + i * 256;
            if (BF4 % 256 == 0 || j < BF4) {
                int k = j / (BN / 4), n4 = (j % (BN / 4)) << 2;
                cp_async16(&Bs[buf][k * BSTR + n4],
                           &B[(size_t)(k0 + k) * ldb + bn + n4]);
            }
        }
        asm volatile("cp.async.commit_group;\n");
    };

    issue(0, 0);

    for (int kt = 0; kt < ntiles; kt++) {
        if (kt + 1 < ntiles) {
            issue((kt + 1) & 1, (kt + 1) * BK);
            asm volatile("cp.async.wait_group 1;\n");
        } else {
            asm volatile("cp.async.wait_group 0;\n");
        }
        __syncthreads();

        const float* as = As[kt & 1];
        const float* bs = Bs[kt & 1];

        // ---- load + split fragments (one m16n8k16 step covers BK=16) ----
        uint32_t ahi[MT][4], alo[MT][4];
#pragma unroll
        for (int mt = 0; mt < MT; mt++) {
            int m0 = wm + mt * 16 + lr;
            float2 f00 = *(const float2*)&as[m0 * ASTR + 2 * lc];
            float2 f10 = *(const float2*)&as[(m0 + 8) * ASTR + 2 * lc];
            float2 f01 = *(const float2*)&as[m0 * ASTR + 2 * lc + 8];
            float2 f11 = *(const float2*)&as[(m0 + 8) * ASTR + 2 * lc + 8];
            bf16split2(f00.x, f00.y, ahi[mt][0], alo[mt][0]);
            bf16split2(f10.x, f10.y, ahi[mt][1], alo[mt][1]);
            bf16split2(f01.x, f01.y, ahi[mt][2], alo[mt][2]);
            bf16split2(f11.x, f11.y, ahi[mt][3], alo[mt][3]);
        }
        uint32_t bhi[NT][2], blo[NT][2];
#pragma unroll
        for (int nt = 0; nt < NT; nt++) {
            int n0 = wn + nt * 8 + lr;
            float fb0 = bs[(2 * lc) * BSTR + n0];
            float fb1 = bs[(2 * lc + 1) * BSTR + n0];
            float fb2 = bs[(2 * lc + 8) * BSTR + n0];
            float fb3 = bs[(2 * lc + 9) * BSTR + n0];
            bf16split2(fb0, fb1, bhi[nt][0], blo[nt][0]);
            bf16split2(fb2, fb3, bhi[nt][1], blo[nt][1]);
        }

#pragma unroll
        for (int mt = 0; mt < MT; mt++)
#pragma unroll
            for (int nt = 0; nt < NT; nt++) {
                mma_bf16(acc[mt][nt], ahi[mt], bhi[nt]);
                mma_bf16(acc[mt][nt], ahi[mt], blo[nt]);
                mma_bf16(acc[mt][nt], alo[mt], bhi[nt]);
            }
        __syncthreads();
    }

    // ---- epilogue ----
#pragma unroll
    for (int mt = 0; mt < MT; mt++) {
        int row0 = bm + wm + mt * 16 + lr;
#pragma unroll
        for (int nt = 0; nt < NT; nt++) {
            int col = bn + wn + nt * 8 + lc * 2;
            float o0 = acc[mt][nt][0], o1 = acc[mt][nt][1];
            float o2 = acc[mt][nt][2], o3 = acc[mt][nt][3];
            if (EPI >= 1) {
                float bb0 = __ldg(&bias[col]), bb1 = __ldg(&bias[col + 1]);
                o0 += bb0; o1 += bb1; o2 += bb0; o3 += bb1;
            }
            if (EPI == 2) {
                o0 = softplus_f(o0); o1 = softplus_f(o1);
                o2 = softplus_f(o2); o3 = softplus_f(o3);
            }
            *(float2*)&C[(size_t)row0 * ldc + col]       = make_float2(o0, o1);
            *(float2*)&C[(size_t)(row0 + 8) * ldc + col] = make_float2(o2, o3);
        }
    }
}

// ---------------- causal depthwise conv (K=4) + SiLU --------------------------
__global__ void conv_silu_kernel(const float* __restrict__ xz,
                                 const float* __restrict__ conv_w,
                                 const float* __restrict__ conv_b,
                                 float* __restrict__ out)
{
    int idx = blockIdx.x * blockDim.x + threadIdx.x;
    int d = idx & (DINsz - 1);
    int t = idx >> 10;
    int l = t & (Lsz - 1);

    float acc = __ldg(&conv_b[d]);
#pragma unroll
    for (int k = 0; k < KCsz; k++) {
        int ls = l + k - (KCsz - 1);
        if (ls >= 0)
            acc = fmaf(xz[(size_t)(t + k - (KCsz - 1)) * (2 * DINsz) + d],
                       __ldg(&conv_w[d * KCsz + k]), acc);
    }
    float s = 1.f / (1.f + expf(-acc));
    out[idx] = acc * s;
}

// ---------------- selective scan (fused skip + gate) ---------------------------
__global__ void scan_kernel(const float* __restrict__ dt,
                            const float* __restrict__ xdbl,
                            const float* __restrict__ xcs,
                            const float* __restrict__ xz,
                            const float* __restrict__ A_log,
                            const float* __restrict__ D_skip,
                            float* __restrict__ y)
{
    const int b = blockIdx.y;
    const int d = blockIdx.x * 32 + threadIdx.x;
    const int lane = threadIdx.x;

    float An[NSTsz];
#pragma unroll
    for (int n = 0; n < NSTsz; n++) An[n] = -expf(A_log[d * NSTsz + n]);

    float h[NSTsz];
#pragma unroll
    for (int n = 0; n < NSTsz; n++) h[n] = 0.f;

    const float Dv = D_skip[d];
    __shared__ float sBC[32];

    for (int l = 0; l < Lsz; l++) {
        const int t = b * Lsz + l;
        const float dtv = dt[(size_t)t * DINsz + d];
        const float xv  = xcs[(size_t)t * DINsz + d];
        sBC[lane] = xdbl[(size_t)t * 64 + DTRsz + lane];
        __syncwarp();

        const float dtx = dtv * xv;
        float yv = 0.f;
#pragma unroll
        for (int n = 0; n < NSTsz; n++) {
            float dA = __expf(dtv * An[n]);
            h[n] = fmaf(h[n], dA, dtx * sBC[n]);
            yv = fmaf(h[n], sBC[NSTsz + n], yv);
        }
        const float zv = xz[(size_t)t * (2 * DINsz) + DINsz + d];
        const float sz = zv / (1.f + __expf(-zv));
        y[(size_t)t * DINsz + d] = (yv + Dv * xv) * sz;
        __syncwarp();
    }
}

// ---------------- LayerNorm over 512 (one warp per row, in place) --------------
__global__ void ln_kernel(float* __restrict__ m,
                          const float* __restrict__ g,
                          const float* __restrict__ b)
{
    const int warp = threadIdx.x >> 5;
    const int lane = threadIdx.x & 31;
    const int row = blockIdx.x * 8 + warp;

    float4* p = (float4*)(m + (size_t)row * BDsz);
    float4 v[4];
    float s = 0.f, ss = 0.f;
#pragma unroll
    for (int i = 0; i < 4; i++) {
        v[i] = p[lane + i * 32];
        s  += v[i].x + v[i].y + v[i].z + v[i].w;
        ss += v[i].x * v[i].x + v[i].y * v[i].y + v[i].z * v[i].z + v[i].w * v[i].w;
    }
#pragma unroll
    for (int o = 16; o > 0; o >>= 1) {
        s  += __shfl_xor_sync(0xFFFFFFFF, s, o);
        ss += __shfl_xor_sync(0xFFFFFFFF, ss, o);
    }
    const float mu = s * (1.f / BDsz);
    const float var = ss * (1.f / BDsz) - mu * mu;
    const float r = rsqrtf(var + 1e-5f);
#pragma unroll
    for (int i = 0; i < 4; i++) {
        int col = (lane + i * 32) * 4;
        float4 o;
        o.x = (v[i].x - mu) * r * __ldg(&g[col + 0]) + __ldg(&b[col + 0]);
        o.y = (v[i].y - mu) * r * __ldg(&g[col + 1]) + __ldg(&b[col + 1]);
        o.z = (v[i].z - mu) * r * __ldg(&g[col + 2]) + __ldg(&b[col + 2]);
        o.w = (v[i].w - mu) * r * __ldg(&g[col + 3]) + __ldg(&b[col + 3]);
        p[lane + i * 32] = o;
    }
}

// ------------------------------- launch ---------------------------------------
extern "C" void kernel_launch(void* const* d_in, const int* in_sizes, int n_in,
                              void* d_out, int out_size)
{
    const float* x      = (const float*)d_in[0];
    const float* W_down = (const float*)d_in[1];
    const float* b_down = (const float*)d_in[2];
    const float* W_in   = (const float*)d_in[3];
    const float* conv_w = (const float*)d_in[4];
    const float* conv_b = (const float*)d_in[5];
    const float* W_x    = (const float*)d_in[6];
    const float* W_dt   = (const float*)d_in[7];
    const float* b_dt   = (const float*)d_in[8];
    const float* A_log  = (const float*)d_in[9];
    const float* D_skip = (const float*)d_in[10];
    const float* W_out  = (const float*)d_in[11];
    const float* ln_g   = (const float*)d_in[12];
    const float* ln_b   = (const float*)d_in[13];
    const float* W_up   = (const float*)d_in[14];
    const float* b_up   = (const float*)d_in[15];
    float* out = (float*)d_out;

    float *ph, *pxz, *pxcs, *pxdbl, *pdt, *py, *pm;
    cudaGetSymbolAddress((void**)&ph,    g_h);
    cudaGetSymbolAddress((void**)&pxz,   g_xz);
    cudaGetSymbolAddress((void**)&pxcs,  g_xcs);
    cudaGetSymbolAddress((void**)&pxdbl, g_xdbl);
    cudaGetSymbolAddress((void**)&pdt,   g_dt);
    cudaGetSymbolAddress((void**)&py,    g_y);
    cudaGetSymbolAddress((void**)&pm,    g_m);

    const int M = Tsz;
    dim3 blk(256);

    // 1) h = x @ W_down + b_down      [16384,1024]x[1024,512]
    mma_gemm<128, 64, 1><<<dim3(BDsz / 128, M / 128), blk>>>(
        M, BDsz, Dsz, Dsz, BDsz, BDsz, x, W_down, b_down, ph);

    // 2) xz = h @ W_in                [16384,512]x[512,2048]
    mma_gemm<128, 64, 0><<<dim3(2 * DINsz / 128, M / 128), blk>>>(
        M, 2 * DINsz, BDsz, BDsz, 2 * DINsz, 2 * DINsz, ph, W_in, nullptr, pxz);

    // 3) conv(K=4, causal) + silu -> xcs
    conv_silu_kernel<<<(Tsz * DINsz) / 256, 256>>>(pxz, conv_w, conv_b, pxcs);

    // 4) x_dbl = xcs @ W_x            [16384,1024]x[1024,64]
    mma_gemm<64, 32, 0><<<dim3(1, M / 128), blk>>>(
        M, 64, DINsz, DINsz, 64, 64, pxcs, W_x, nullptr, pxdbl);

    // 5) dt = softplus(x_dbl[:, :32] @ W_dt + b_dt)   [16384,32]x[32,1024]
    mma_gemm<128, 64, 2><<<dim3(DINsz / 128, M / 128), blk>>>(
        M, DINsz, DTRsz, 64, DINsz, DINsz, pxdbl, W_dt, b_dt, pdt);

    // 6) selective scan + skip + gate -> y
    scan_kernel<<<dim3(DINsz / 32, Bsz), 32>>>(pdt, pxdbl, pxcs, pxz, A_log, D_skip, py);

    // 7) m = y @ W_out                [16384,1024]x[1024,512]
    mma_gemm<128, 64, 0><<<dim3(BDsz / 128, M / 128), blk>>>(
        M, BDsz, DINsz, DINsz, BDsz, BDsz, py, W_out, nullptr, pm);

    // 8) LayerNorm(512) in place
    ln_kernel<<<M / 8, 256>>>(pm, ln_g, ln_b);

    // 9) out = m @ W_up + b_up        [16384,512]x[512,1024]
    mma_gemm<128, 64, 1><<<dim3(Dsz / 128, M / 128), blk>>>(
        M, Dsz, BDsz, BDsz, Dsz, Dsz, pm, W_up, b_up, out);
}